// round 16
// baseline (speedup 1.0000x reference)
#include <cuda_runtime.h>

#define NW  12
#define DIM 4096
#define EPB 4                 // elements per block
#define TPB (EPB * 48)        // 48 threads per element: 12 wires x 4 columns

// ---------------------------------------------------------------------------
// Transfer-matrix evaluation, one thread per (output wire, boundary column).
// Math identical to the R15-passing kernel; parallelized per-wire instead of
// the nested single sweep: thread (w,col) evolves its column 4-vector through
// sites 1..nsites (nsites = w for 1<=w<=10, else 11), then applies
//   w in 1..10 : bridge at u=w+1, identity tail N(w), site-0 cap (D_0)
//   w == 11   : site-0 cap with D_0 over the full chain
//   w == 0    : site-0 identity cap (S_0 = {1..11})
// Per-wire factors are computed once per element (12 lanes) into smem.
// Columns reduce via 2 shuffles; wires reduce via smem.
// ---------------------------------------------------------------------------

__global__ __launch_bounds__(TPB) void qtm_kernel(
    const float* __restrict__ state_batch,
    const float* __restrict__ params,
    const float* __restrict__ head_w,
    const float* __restrict__ head_b,
    float* __restrict__ out, int nbatch) {
    __shared__ float sf0r[EPB][NW], sf0i[EPB][NW], sf1r[EPB][NW], sf1i[EPB][NW];
    __shared__ float scg[EPB][NW], ssg[EPB][NW], spart[EPB][NW];

    const int tid  = threadIdx.x;
    const int eid  = tid / 48;
    const int etid = tid % 48;
    const int w    = etid >> 2;
    const int col  = etid & 3;
    const int g = col & 1, gp = col >> 1;
    const int b  = blockIdx.x * EPB + eid;
    const bool valid = b < nbatch;
    const int  bb = valid ? b : 0;

    // --- prologue: 12 lanes per element compute per-wire factors into smem
    if (etid < NW) {
        int w2 = etid;
        float ang = state_batch[(size_t)bb * DIM + w2];
        float th = 0.5f * (ang + params[2 * w2]);
        float ph = 0.5f * params[2 * w2 + 1];
        float sh, ch, sp, cp;
        __sincosf(th, &sh, &ch);
        __sincosf(ph, &sp, &cp);
        sf0r[eid][w2] = cp * ch; sf0i[eid][w2] = -sp * ch;
        sf1r[eid][w2] = cp * sh; sf1i[eid][w2] =  sp * sh;
        float t1 = params[2 * NW + 2 * w2];      // FULL angle for D
        float s1, c1;
        __sincosf(t1, &s1, &c1);
        scg[eid][w2] = c1; ssg[eid][w2] = s1;
    }
    __syncthreads();

    const float c0 = scg[eid][0], s0 = ssg[eid][0];
    const float hw = head_w[w];

    // --- this lane's boundary weight W = f_0(g) conj(f_0(g'))
    {
    }
    float ar = g ? sf1r[eid][0] : sf0r[eid][0];
    float ai = g ? sf1i[eid][0] : sf0i[eid][0];
    float br = gp ? sf1r[eid][0] : sf0r[eid][0];
    float bi = gp ? sf1i[eid][0] : sf0i[eid][0];
    const float Wr = ar * br + ai * bi;
    const float Wi = ai * br - ar * bi;

    // --- identity-tail scalar NA(w) for w in 1..10 (NB = 1-NA)
    float NAw = 1.f;
#pragma unroll
    for (int u = 11; u >= 3; u--) {
        if (u >= w + 2 && w >= 1 && w <= 10) {
            float n0 = sf0r[eid][u] * sf0r[eid][u] + sf0i[eid][u] * sf0i[eid][u];
            NAw = NAw * n0 + (1.f - NAw) * (1.f - n0);
        }
    }

    // --- column state: complex 4-vector, pair idx = P + 2P'; init e_col
    float m0r = (col == 0), m0i = 0.f;
    float m1r = (col == 1), m1i = 0.f;
    float m2r = (col == 2), m2i = 0.f;
    float m3r = (col == 3), m3i = 0.f;

    const int nsites = (w >= 1 && w <= 10) ? w : 11;

#pragma unroll
    for (int v = 1; v <= 11; v++) {
        if (v <= nsites) {
            const float fr0 = sf0r[eid][v], fi0 = sf0i[eid][v];
            const float fr1 = sf1r[eid][v], fi1 = sf1i[eid][v];
            const float cv = scg[eid][v], sv = ssg[eid][v];
            // A: a[Pn][P'p] = f(0)m[Pn][P'p] + f(1)m[Pn^1][P'p]
            float a00r = fr0*m0r - fi0*m0i + fr1*m1r - fi1*m1i;
            float a00i = fr0*m0i + fi0*m0r + fr1*m1i + fi1*m1r;
            float a10r = fr1*m0r - fi1*m0i + fr0*m1r - fi0*m1i;
            float a10i = fr1*m0i + fi1*m0r + fr0*m1i + fi0*m1r;
            float a01r = fr0*m2r - fi0*m2i + fr1*m3r - fi1*m3i;
            float a01i = fr0*m2i + fi0*m2r + fr1*m3i + fi1*m3r;
            float a11r = fr1*m2r - fi1*m2i + fr0*m3r - fi0*m3i;
            float a11i = fr1*m2i + fi1*m2r + fr0*m3i + fi0*m3r;
            // B: b[Pn][P'n] = cf(0)a[Pn][P'n] + cf(1)a[Pn][P'n^1]
            float b00r = fr0*a00r + fi0*a00i + fr1*a01r + fi1*a01i;
            float b00i = fr0*a00i - fi0*a00r + fr1*a01i - fi1*a01r;
            float b10r = fr0*a10r + fi0*a10i + fr1*a11r + fi1*a11i;
            float b10i = fr0*a10i - fi0*a10r + fr1*a11i - fi1*a11r;
            float b01r = fr1*a00r + fi1*a00i + fr0*a01r + fi0*a01i;
            float b01i = fr1*a00i - fi1*a00r + fr0*a01i - fi0*a01r;
            float b11r = fr1*a10r + fi1*a10i + fr0*a11r + fi0*a11i;
            float b11i = fr1*a10i - fi1*a10r + fr0*a11i - fi0*a11r;
            // C: × D[P'n][Pn]
            m0r =  cv*b00r; m0i =  cv*b00i;
            m1r = -sv*b10r; m1i = -sv*b10i;
            m2r = -sv*b01r; m2i = -sv*b01i;
            m3r = -cv*b11r; m3i = -cv*b11i;
        }
    }

    // --- epilogue per wire class
    float o;
    if (w >= 1 && w <= 10) {
        const int u = w + 1;
        const float gr0 = sf0r[eid][u], gi0 = sf0i[eid][u];
        const float gr1 = sf1r[eid][u], gi1 = sf1i[eid][u];
        float e00r = gr0*m0r - gi0*m0i + gr1*m1r - gi1*m1i;
        float e00i = gr0*m0i + gi0*m0r + gr1*m1i + gi1*m1r;
        float e01r = gr0*m2r - gi0*m2i + gr1*m3r - gi1*m3i;
        float e01i = gr0*m2i + gi0*m2r + gr1*m3i + gi1*m3r;
        float e10r = gr1*m0r - gi1*m0i + gr0*m1r - gi0*m1i;
        float e10i = gr1*m0i + gi1*m0r + gr0*m1i + gi0*m1r;
        float e11r = gr1*m2r - gi1*m2i + gr0*m3r - gi0*m3i;
        float e11i = gr1*m2i + gi1*m2r + gr0*m3i + gi0*m3r;
        float t0r = gr0*e00r + gi0*e00i + gr1*e01r + gi1*e01i;
        float t0i = gr0*e00i - gi0*e00r + gr1*e01i - gi1*e01r;
        float t1r = gr1*e10r + gi1*e10i + gr0*e11r + gi0*e11i;
        float t1i = gr1*e10i - gi1*e10r + gr0*e11i - gi0*e11r;
        // z = N(w) t with NB = 1-NA
        float z0r = t1r + NAw*(t0r - t1r), z0i = t1i + NAw*(t0i - t1i);
        float z1r = t0r + NAw*(t1r - t0r), z1i = t0i + NAw*(t1i - t0i);
        float Sr, Si;
        if (g == gp) {
            float d0 = g ? -c0 : c0;
            Sr = d0 * (z0r - z1r); Si = d0 * (z0i - z1i);
        } else {
            Sr = -s0 * (z0r + z1r); Si = -s0 * (z0i + z1i);
        }
        o = Wr * Sr - Wi * Si;
    } else {
        float mr[4] = {m0r, m1r, m2r, m3r};
        float mi[4] = {m0i, m1i, m2i, m3i};
        float acc = 0.f;
        if (w == 11) {
#pragma unroll
            for (int idx = 0; idx < 4; idx++) {
                int h = idx & 1, hp = idx >> 1;
                int y = h ^ g, yp = hp ^ gp;
                float wmr = Wr * mr[idx] - Wi * mi[idx];
                float Dv = (y == yp) ? (y ? -c0 : c0) : (-s0);
                acc += Dv * wmr;
            }
        } else {  // w == 0: identity cap
#pragma unroll
            for (int idx = 0; idx < 4; idx++) {
                int h = idx & 1, hp = idx >> 1;
                if ((h ^ g) == (hp ^ gp))
                    acc += Wr * mr[idx] - Wi * mi[idx];
            }
        }
        o = acc;
    }

    // --- reduce the 4 column lanes (quads are lane-contiguous: 4 | 48, 4 | 32)
    o += __shfl_xor_sync(0xffffffffu, o, 1);
    o += __shfl_xor_sync(0xffffffffu, o, 2);
    if (col == 0) spart[eid][w] = hw * o;
    __syncthreads();

    if (etid == 0 && valid) {
        float t = head_b[0];
#pragma unroll
        for (int i = 0; i < NW; i++) t += spart[eid][i];
        out[b] = t;
    }
}

// ---------------------------------------------------------------------------

extern "C" void kernel_launch(void* const* d_in, const int* in_sizes, int n_in,
                              void* d_out, int out_size) {
    const float* state_batch = (const float*)d_in[0];
    const float* params      = (const float*)d_in[1];
    const float* head_w      = (const float*)d_in[2];
    const float* head_b      = (const float*)d_in[3];
    float* out = (float*)d_out;

    int blocks = (out_size + EPB - 1) / EPB;
    qtm_kernel<<<blocks, TPB>>>(state_batch, params, head_w, head_b, out, out_size);
}

// round 17
// speedup vs baseline: 1.3247x; 1.3247x over previous
#include <cuda_runtime.h>

#define NW  12
#define DIM 4096
#define EPB 8
#define TPB 64

// ---------------------------------------------------------------------------
// Parallel-prefix transfer-matrix evaluation. Math identical to the R15
// passing kernel; the site chain T_11...T_1 is split associatively:
//   warp A (tid<32), 4 lanes/element (one per boundary column (g,g')):
//     evolves M_v = T_v..T_1 e_col for v=1..5, emitting wires 1..5 inline
//     via the (bridge u=v+1, tail NA(v), site-0 cap) epilogue.
//   warp B (tid>=32), 4 lanes/element (one per basis vector e_j):
//     evolves Q_v = T_v..T_6 e_j for v=6..11; for wires 6..10 records the
//     two linear functionals z0-z1, z0+z1 of its partial vector; writes its
//     final vector Q_11 e_j.
// All epilogues are C-linear in the state, so
//   L(M_w e_col) = sum_j (M_5 e_col)_j * L(Q_w e_j),
// and warp A finishes wires 6..11 and 0 by contracting B's scalars/vectors
// with its own m5 after one __syncthreads. A and B are separate warps ->
// no divergence serialization (the R16 mistake).
// ---------------------------------------------------------------------------

__global__ __launch_bounds__(TPB) void qtm_kernel(
    const float* __restrict__ state_batch,
    const float* __restrict__ params,
    const float* __restrict__ head_w,
    const float* __restrict__ head_b,
    float* __restrict__ out, int nbatch) {
    __shared__ float sf0r[EPB][NW], sf0i[EPB][NW], sf1r[EPB][NW], sf1i[EPB][NW];
    __shared__ float scg[EPB][NW], ssg[EPB][NW];
    __shared__ float suv[EPB][5][4][4];  // [w-6][j][{ur,ui,vr,vi}]
    __shared__ float sq [EPB][4][4][2];  // [j][idx][{r,i}]

    const int tid   = threadIdx.x;
    const bool isA  = tid < 32;
    const int lane  = tid & 31;
    const int e     = lane >> 2;
    const int l4    = lane & 3;          // col (A) or j (B)
    const int b     = blockIdx.x * EPB + e;
    const bool valid = b < nbatch;
    const int bb    = valid ? b : 0;

    // ---- prologue: per-wire factors. A lane: wires l4, l4+4. B lane: l4+8.
    {
        int w2 = isA ? l4 : (l4 + 8);
        int nrounds = isA ? 2 : 1;
        for (int r = 0; r < nrounds; r++, w2 += 4) {
            float ang = state_batch[(size_t)bb * DIM + w2];
            float th = 0.5f * (ang + params[2 * w2]);
            float ph = 0.5f * params[2 * w2 + 1];
            float sh, ch, sp, cp;
            __sincosf(th, &sh, &ch);
            __sincosf(ph, &sp, &cp);
            sf0r[e][w2] = cp * ch; sf0i[e][w2] = -sp * ch;
            sf1r[e][w2] = cp * sh; sf1i[e][w2] =  sp * sh;
            float a1 = params[2 * NW + 2 * w2];      // FULL angle for D
            float s1, c1;
            __sincosf(a1, &s1, &c1);
            scg[e][w2] = c1; ssg[e][w2] = s1;
        }
    }
    __syncthreads();

    // ---- identity-tail NA table (NB = 1-NA)
    float NA[11];
    NA[10] = 1.f;
#pragma unroll
    for (int w = 9; w >= 1; w--) {
        int u = w + 2;
        float n0 = sf0r[e][u] * sf0r[e][u] + sf0i[e][u] * sf0i[e][u];
        NA[w] = NA[w + 1] * n0 + (1.f - NA[w + 1]) * (1.f - n0);
    }

    // ---- column/basis state: complex 4-vector, pair idx = P + 2P'
    float m0r = (l4 == 0), m0i = 0.f;
    float m1r = (l4 == 1), m1i = 0.f;
    float m2r = (l4 == 2), m2i = 0.f;
    float m3r = (l4 == 3), m3i = 0.f;
    float o = 0.f;

    const float c0 = scg[e][0], s0 = ssg[e][0];
    const int g = l4 & 1, gp = l4 >> 1;
    // boundary weight W = f_0(g) conj(f_0(g'))  (used by A only)
    float ar = g ? sf1r[e][0] : sf0r[e][0];
    float ai = g ? sf1i[e][0] : sf0i[e][0];
    float br = gp ? sf1r[e][0] : sf0r[e][0];
    float bi = gp ? sf1i[e][0] : sf0i[e][0];
    const float Wr = ar * br + ai * bi;
    const float Wi = ai * br - ar * bi;

#define SITE(v) { \
    const float fr0 = sf0r[e][v], fi0 = sf0i[e][v]; \
    const float fr1 = sf1r[e][v], fi1 = sf1i[e][v]; \
    const float cv = scg[e][v], sv = ssg[e][v]; \
    float a00r = fr0*m0r - fi0*m0i + fr1*m1r - fi1*m1i; \
    float a00i = fr0*m0i + fi0*m0r + fr1*m1i + fi1*m1r; \
    float a10r = fr1*m0r - fi1*m0i + fr0*m1r - fi0*m1i; \
    float a10i = fr1*m0i + fi1*m0r + fr0*m1i + fi0*m1r; \
    float a01r = fr0*m2r - fi0*m2i + fr1*m3r - fi1*m3i; \
    float a01i = fr0*m2i + fi0*m2r + fr1*m3i + fi1*m3r; \
    float a11r = fr1*m2r - fi1*m2i + fr0*m3r - fi0*m3i; \
    float a11i = fr1*m2i + fi1*m2r + fr0*m3i + fi0*m3r; \
    float b00r = fr0*a00r + fi0*a00i + fr1*a01r + fi1*a01i; \
    float b00i = fr0*a00i - fi0*a00r + fr1*a01i - fi1*a01r; \
    float b10r = fr0*a10r + fi0*a10i + fr1*a11r + fi1*a11i; \
    float b10i = fr0*a10i - fi0*a10r + fr1*a11i - fi1*a11r; \
    float b01r = fr1*a00r + fi1*a00i + fr0*a01r + fi0*a01i; \
    float b01i = fr1*a00i - fi1*a00r + fr0*a01i - fi0*a01r; \
    float b11r = fr1*a10r + fi1*a10i + fr0*a11r + fi0*a11i; \
    float b11i = fr1*a10i - fi1*a10r + fr0*a11i - fi0*a11r; \
    m0r =  cv*b00r; m0i =  cv*b00i; \
    m1r = -sv*b10r; m1i = -sv*b10i; \
    m2r = -sv*b01r; m2i = -sv*b01i; \
    m3r = -cv*b11r; m3i = -cv*b11i; }

// bridge at site u + identity tail NAv -> z0, z1 (declares Z names)
#define ZSTAGE(u, NAv, Z0R, Z0I, Z1R, Z1I) \
    float Z0R, Z0I, Z1R, Z1I; { \
    const float gr0 = sf0r[e][u], gi0 = sf0i[e][u]; \
    const float gr1 = sf1r[e][u], gi1 = sf1i[e][u]; \
    float e00r = gr0*m0r - gi0*m0i + gr1*m1r - gi1*m1i; \
    float e00i = gr0*m0i + gi0*m0r + gr1*m1i + gi1*m1r; \
    float e01r = gr0*m2r - gi0*m2i + gr1*m3r - gi1*m3i; \
    float e01i = gr0*m2i + gi0*m2r + gr1*m3i + gi1*m3r; \
    float e10r = gr1*m0r - gi1*m0i + gr0*m1r - gi0*m1i; \
    float e10i = gr1*m0i + gi1*m0r + gr0*m1i + gi0*m1r; \
    float e11r = gr1*m2r - gi1*m2i + gr0*m3r - gi0*m3i; \
    float e11i = gr1*m2i + gi1*m2r + gr0*m3i + gi0*m3r; \
    float tt0r = gr0*e00r + gi0*e00i + gr1*e01r + gi1*e01i; \
    float tt0i = gr0*e00i - gi0*e00r + gr1*e01i - gi1*e01r; \
    float tt1r = gr1*e10r + gi1*e10i + gr0*e11r + gi0*e11i; \
    float tt1i = gr1*e10i - gi1*e10r + gr0*e11i - gi0*e11r; \
    Z0R = tt1r + (NAv)*(tt0r - tt1r); Z0I = tt1i + (NAv)*(tt0i - tt1i); \
    Z1R = tt0r + (NAv)*(tt1r - tt0r); Z1I = tt0i + (NAv)*(tt1i - tt0i); }

    if (isA) {
        // warp A: sites 1..5, wires 1..5 inline; m ends as M5 e_col
#pragma unroll
        for (int v = 1; v <= 5; v++) {
            SITE(v);
            ZSTAGE(v + 1, NA[v], z0r, z0i, z1r, z1i);
            float Sr, Si;
            if (g == gp) {
                float d0 = g ? -c0 : c0;
                Sr = d0 * (z0r - z1r); Si = d0 * (z0i - z1i);
            } else {
                Sr = -s0 * (z0r + z1r); Si = -s0 * (z0i + z1i);
            }
            o = fmaf(head_w[v], Wr * Sr - Wi * Si, o);
        }
    } else {
        // warp B: sites 6..11; record wire 6..10 functionals; write Q11 e_j
#pragma unroll
        for (int v = 6; v <= 11; v++) {
            SITE(v);
            if (v <= 10) {
                ZSTAGE(v + 1, NA[v], z0r, z0i, z1r, z1i);
                suv[e][v - 6][l4][0] = z0r - z1r;
                suv[e][v - 6][l4][1] = z0i - z1i;
                suv[e][v - 6][l4][2] = z0r + z1r;
                suv[e][v - 6][l4][3] = z0i + z1i;
            }
        }
        sq[e][l4][0][0] = m0r; sq[e][l4][0][1] = m0i;
        sq[e][l4][1][0] = m1r; sq[e][l4][1][1] = m1i;
        sq[e][l4][2][0] = m2r; sq[e][l4][2][1] = m2i;
        sq[e][l4][3][0] = m3r; sq[e][l4][3][1] = m3i;
    }
    __syncthreads();

    if (isA) {
        const float m5r[4] = {m0r, m1r, m2r, m3r};
        const float m5i[4] = {m0i, m1i, m2i, m3i};
        // wires 6..10: L(M_w e_col) = sum_j m5_j * L(Q_w e_j)
        const int off = (g == gp) ? 0 : 2;
        const float dfac = (g == gp) ? (g ? -c0 : c0) : (-s0);
#pragma unroll
        for (int w = 6; w <= 10; w++) {
            float Xr = 0.f, Xi = 0.f;
#pragma unroll
            for (int j = 0; j < 4; j++) {
                float xr = suv[e][w - 6][j][off + 0];
                float xi = suv[e][w - 6][j][off + 1];
                Xr += xr * m5r[j] - xi * m5i[j];
                Xi += xr * m5i[j] + xi * m5r[j];
            }
            float Sr = dfac * Xr, Si = dfac * Xi;
            o = fmaf(head_w[w], Wr * Sr - Wi * Si, o);
        }
        // M11 e_col = Q11 (M5 e_col)
        float M11r[4], M11i[4];
#pragma unroll
        for (int idx = 0; idx < 4; idx++) {
            float accr = 0.f, acci = 0.f;
#pragma unroll
            for (int j = 0; j < 4; j++) {
                float qr = sq[e][j][idx][0], qi = sq[e][j][idx][1];
                accr += qr * m5r[j] - qi * m5i[j];
                acci += qr * m5i[j] + qi * m5r[j];
            }
            M11r[idx] = accr; M11i[idx] = acci;
        }
        // wires 11 (D_0 cap) and 0 (identity cap)
        float acc11 = 0.f, acc0 = 0.f;
#pragma unroll
        for (int idx = 0; idx < 4; idx++) {
            int h = idx & 1, hp = idx >> 1;
            int y = h ^ g, yp = hp ^ gp;
            float wmr = Wr * M11r[idx] - Wi * M11i[idx];
            float Dv = (y == yp) ? (y ? -c0 : c0) : (-s0);
            acc11 += Dv * wmr;
            if (y == yp) acc0 += wmr;
        }
        o += head_w[11] * acc11 + head_w[0] * acc0;

        // reduce the 4 column lanes (contiguous quads within warp A)
        o += __shfl_xor_sync(0xffffffffu, o, 1);
        o += __shfl_xor_sync(0xffffffffu, o, 2);
        if (l4 == 0 && valid) out[b] = o + head_b[0];
    }
#undef SITE
#undef ZSTAGE
}

// ---------------------------------------------------------------------------

extern "C" void kernel_launch(void* const* d_in, const int* in_sizes, int n_in,
                              void* d_out, int out_size) {
    const float* state_batch = (const float*)d_in[0];
    const float* params      = (const float*)d_in[1];
    const float* head_w      = (const float*)d_in[2];
    const float* head_b      = (const float*)d_in[3];
    float* out = (float*)d_out;

    int blocks = (out_size + EPB - 1) / EPB;
    qtm_kernel<<<blocks, TPB>>>(state_batch, params, head_w, head_b, out, out_size);
}